// round 11
// baseline (speedup 1.0000x reference)
#include <cuda_runtime.h>
#include <math_constants.h>

#define HH 256
#define WW 256
#define NIMG 512          // B*C = 8*64
#define CCH 64
#define HWSZ 65536        // 256*256
#define NSEG 14           // segments per image (4x19 + 10x18 rows)

// Scratch (static device globals — no runtime allocation)
__device__ float g_cmax32[NIMG * HH * 32];    // per-(row, lane=8col) max of dst
__device__ float g_segmax[NIMG * NSEG];       // per-segment max of dst

__device__ __forceinline__ int rrow(int r) {
    return r < 0 ? -r : (r >= HH ? 2*HH - 2 - r : r);
}

// clamp dynamic local-array index into [0,4] — prevents speculative
// out-of-frame LDL when ptxas flattens the border branches into selects
#define CL(i) (min(max((int)(i), 0), 4))

// ---------------------------------------------------------------------------
// Pass A: Harris response R -> per-lane chunk maxes of the 3x3-dilated field
// (dst itself never materialized), segment maxes, out=x copy fused into the
// stencil row loads. One warp per (image, segment); lane owns 8 cols.
// All FP contractions pinned with explicit fmaf so the apply path can
// recompute dst bit-identically.
// ---------------------------------------------------------------------------

// Load x row r (reflect-101). If the REQUESTED row lies in this segment,
// also store it to out (each segment row passes through here exactly once).
#define LOAD_XROW(r, dst_)  do {                                              \
    int rq__ = (r);                                                           \
    int rr__ = (rq__ < 0) ? -rq__ : ((rq__ >= HH) ? (2*HH - 2 - rq__) : rq__);\
    const float4* p__ = reinterpret_cast<const float4*>(xim + rr__ * WW + cb);\
    float4 q0__ = p__[0], q1__ = p__[1];                                      \
    dst_[0]=q0__.x; dst_[1]=q0__.y; dst_[2]=q0__.z; dst_[3]=q0__.w;           \
    dst_[4]=q1__.x; dst_[5]=q1__.y; dst_[6]=q1__.z; dst_[7]=q1__.w;           \
    if ((unsigned)(rq__ - r0) < (unsigned)seglen) {                           \
        float4* po__ = reinterpret_cast<float4*>(oim + rq__ * WW + cb);       \
        po__[0] = q0__; po__[1] = q1__;                                       \
    }                                                                         \
} while(0)

#define COMPUTE_DD(row, AX, AXY, AY) do {                                     \
    float xc__[8]; LOAD_XROW((row)+1, xc__);                                  \
    float u__[8], v__[8];                                                     \
    _Pragma("unroll")                                                         \
    for (int i=0;i<8;i++){ u__[i] = fmaf(2.0f, xb[i], xa[i]) + xc__[i];       \
                           v__[i] = xc__[i] - xa[i]; }                        \
    float uL__ = __shfl_up_sync(0xffffffffu, u__[7], 1);                      \
    float uR__ = __shfl_down_sync(0xffffffffu, u__[0], 1);                    \
    float vL__ = __shfl_up_sync(0xffffffffu, v__[7], 1);                      \
    float vR__ = __shfl_down_sync(0xffffffffu, v__[0], 1);                    \
    if (lane == 0)  { uL__ = u__[1]; vL__ = v__[1]; }                         \
    if (lane == 31) { uR__ = u__[6]; vR__ = v__[6]; }                         \
    _Pragma("unroll")                                                         \
    for (int i=0;i<8;i++){                                                    \
        float um1__ = (i==0)? uL__ : u__[i-1];                                \
        float up1__ = (i==7)? uR__ : u__[i+1];                                \
        float vm1__ = (i==0)? vL__ : v__[i-1];                                \
        float vp1__ = (i==7)? vR__ : v__[i+1];                                \
        float dx__ = (up1__ - um1__) * SC;                                    \
        float dy__ = (fmaf(2.0f, v__[i], vm1__) + vp1__) * SC;                \
        AX[i] = dx__*dx__; AXY[i] = dx__*dy__; AY[i] = dy__*dy__;             \
    }                                                                         \
    _Pragma("unroll")                                                         \
    for (int i=0;i<8;i++){ xa[i] = xb[i]; xb[i] = xc__[i]; }                  \
} while(0)

// Horizontal sums + R + per-lane row max h + emit chunkmax row q = PV-1.
#define EMIT_P(PV) do {                                                       \
    float xxL__ = __shfl_up_sync(0xffffffffu, sxx[7],1);                      \
    float xxR__ = __shfl_down_sync(0xffffffffu, sxx[0],1);                    \
    float xyL__ = __shfl_up_sync(0xffffffffu, sxy[7],1);                      \
    float xyR__ = __shfl_down_sync(0xffffffffu, sxy[0],1);                    \
    float yyL__ = __shfl_up_sync(0xffffffffu, syy[7],1);                      \
    float yyR__ = __shfl_down_sync(0xffffffffu, syy[0],1);                    \
    if (lane==0){  xxL__=sxx[1]; xyL__=sxy[1]; yyL__=syy[1]; }                \
    if (lane==31){ xxR__=sxx[6]; xyR__=sxy[6]; yyR__=syy[6]; }                \
    float Rv__[8];                                                            \
    _Pragma("unroll")                                                         \
    for (int i=0;i<8;i++){                                                    \
        float ixx = (((i==0)?xxL__:sxx[i-1]) + sxx[i]) + ((i==7)?xxR__:sxx[i+1]);\
        float ixy = (((i==0)?xyL__:sxy[i-1]) + sxy[i]) + ((i==7)?xyR__:sxy[i+1]);\
        float iyy = (((i==0)?yyL__:syy[i-1]) + syy[i]) + ((i==7)?yyR__:syy[i+1]);\
        float t1__ = ixy * ixy;                                               \
        float det__ = fmaf(ixx, iyy, -t1__);                                  \
        float tr__  = ixx + iyy;                                              \
        float t2__ = tr__ * tr__;                                             \
        Rv__[i] = fmaf(-0.04f, t2__, det__);                                  \
    }                                                                         \
    float RL__ = __shfl_up_sync(0xffffffffu, Rv__[7],1);                      \
    float RR__ = __shfl_down_sync(0xffffffffu, Rv__[0],1);                    \
    if (lane==0)  RL__ = -CUDART_INF_F;                                       \
    if (lane==31) RR__ = -CUDART_INF_F;                                       \
    float hc__ = fmaxf(RL__, RR__);                                           \
    _Pragma("unroll")                                                         \
    for (int i=0;i<8;i++) hc__ = fmaxf(hc__, Rv__[i]);                        \
    int q__ = (PV) - 1;                                                       \
    if (q__ >= r0) {                                                          \
        float cm__ = fmaxf(fmaxf(hb, ha), hc__);                              \
        lmax = fmaxf(lmax, cm__);                                             \
        g_cmax32[((img<<8)+q__)*32 + lane] = cm__;                            \
    }                                                                         \
    hb = ha; ha = hc__;                                                       \
} while(0)

__global__ void __launch_bounds__(32, 16) harris_kernel(const float* __restrict__ x,
                                                        float* __restrict__ out) {
    const int img  = blockIdx.x / NSEG;
    const int seg  = blockIdx.x - img * NSEG;
    const int lane = threadIdx.x;
    const int cb   = lane * 8;
    const float* __restrict__ xim = x + (size_t)img * HWSZ;
    float* __restrict__ oim = out + (size_t)img * HWSZ;

    // 4 segments of 19 rows then 10 of 18 rows (total 256); grid 7168 warps
    // = 3.03 waves at 16 resident blocks/SM (kills wave quantization).
    const int r0     = seg * 18 + min(seg, 4);
    const int seglen = 18 + (seg < 4 ? 1 : 0);
    const int r1     = r0 + seglen;

    const float SC = (1.0f / 12.0f);   // SOBEL_SCALE
    float xa[8], xb[8];
    float p2x[8], p2y[8], p2z[8];      // P2 = dd(p-1)+dd(p)   (xx,xy,yy)
    float cx[8],  cy[8],  cz[8];       // C  = dd(p)
    float ha = -CUDART_INF_F, hb = -CUDART_INF_F;  // h(p-1), h(p-2)
    float lmax = -CUDART_INF_F;

    int pstart;
    if (r0 == 0) {
        LOAD_XROW(-1, xa);
        LOAD_XROW(0,  xb);
        COMPUTE_DD(0, cx, cy, cz);
#pragma unroll
        for (int i=0;i<8;i++){ p2x[i]=cx[i]+cx[i]; p2y[i]=cy[i]+cy[i]; p2z[i]=cz[i]+cz[i]; }
        // peeled p == 0 iteration (emits q=-1: nothing; shifts ha/hb)
        {
            float nx[8], ny[8], nz[8];
            COMPUTE_DD(1, nx, ny, nz);
            float sxx[8], sxy[8], syy[8];
#pragma unroll
            for (int i=0;i<8;i++){ sxx[i]=fmaf(2.0f, nx[i], cx[i]);
                                   sxy[i]=fmaf(2.0f, ny[i], cy[i]);
                                   syy[i]=fmaf(2.0f, nz[i], cz[i]); }
#pragma unroll
            for (int i=0;i<8;i++){ p2x[i]=cx[i]+nx[i]; cx[i]=nx[i];
                                   p2y[i]=cy[i]+ny[i]; cy[i]=ny[i];
                                   p2z[i]=cz[i]+nz[i]; cz[i]=nz[i]; }
            EMIT_P(0);
        }
        pstart = 1;
    } else {
        float d1x[8], d1y[8], d1z[8];
        LOAD_XROW(r0 - 3, xa);
        LOAD_XROW(r0 - 2, xb);
        COMPUTE_DD(r0 - 2, d1x, d1y, d1z);
        COMPUTE_DD(r0 - 1, cx, cy, cz);
#pragma unroll
        for (int i=0;i<8;i++){ p2x[i]=d1x[i]+cx[i]; p2y[i]=d1y[i]+cy[i]; p2z[i]=d1z[i]+cz[i]; }
        pstart = r0 - 1;
    }

    const int pend = (r1 == HH) ? (HH - 1) : (r1 + 1);
#pragma unroll 2
    for (int p = pstart; p < pend; ++p) {
        float nx[8], ny[8], nz[8];
        COMPUTE_DD(p+1, nx, ny, nz);
        float sxx[8], sxy[8], syy[8];
#pragma unroll
        for (int i=0;i<8;i++){ sxx[i]=p2x[i]+nx[i];
                               sxy[i]=p2y[i]+ny[i];
                               syy[i]=p2z[i]+nz[i]; }
#pragma unroll
        for (int i=0;i<8;i++){ p2x[i]=cx[i]+nx[i]; cx[i]=nx[i];
                               p2y[i]=cy[i]+ny[i]; cy[i]=ny[i];
                               p2z[i]=cz[i]+nz[i]; cz[i]=nz[i]; }
        EMIT_P(p);
    }

    if (r1 == HH) {
        // peel p = 255: vertical sum = dd(255) + 2*(p2-dd(255)) (= +2*dd(254))
        float sxx[8], sxy[8], syy[8];
#pragma unroll
        for (int i=0;i<8;i++){
            sxx[i] = fmaf(2.0f, p2x[i] - cx[i], cx[i]);
            sxy[i] = fmaf(2.0f, p2y[i] - cy[i], cy[i]);
            syy[i] = fmaf(2.0f, p2z[i] - cz[i], cz[i]);
        }
        EMIT_P(255);
        // bottom image row: chunkmax(255) = max(h(254), h(255))
        float cm = fmaxf(hb, ha);
        lmax = fmaxf(lmax, cm);
        g_cmax32[((img<<8)+(HH-1))*32 + lane] = cm;
    }

#pragma unroll
    for (int o=16;o;o>>=1) lmax = fmaxf(lmax, __shfl_xor_sync(0xffffffffu, lmax, o));
    if (lane == 0) g_segmax[img * NSEG + seg] = lmax;
}

// ---------------------------------------------------------------------------
// Detect + apply (fused, balanced): 4096 blocks x 256 threads; block covers
// 512 contiguous chunks (32 rows of one image). Both loads (cmax float4 +
// segmax) are issued BEFORE the sync so there is a single latency window.
// Flagged chunks go to a block-smem list; the block's 8 warps redistribute
// them. Apply: recompute dst bit-identical to pass A; then PIXEL-PER-LANE
// conv: lanes 0-15 own the chunk's 16 pixels (channels 0-31), lanes 16-31
// the same pixels (channels 32-63). Per channel the 16 lanes hit 16
// CONSECUTIVE pixels (2 sectors/channel instead of 64 sectors/pixel), all
// 32 loads independent (one latency window), single shfl to merge halves.
// ---------------------------------------------------------------------------
__global__ void __launch_bounds__(256) detect_apply_kernel(
        const float* __restrict__ x, const float* __restrict__ wt,
        const float* __restrict__ bias, float* __restrict__ out) {
    __shared__ float s14[NSEG];
    __shared__ int   slist[512];
    __shared__ int   scount;
    const int img   = blockIdx.x >> 3;
    const int tid   = threadIdx.x;

    // both global loads in flight before the sync
    const float4 v = *reinterpret_cast<const float4*>(
        g_cmax32 + ((size_t)blockIdx.x << 10) + (tid << 2));
    if (tid == 0) scount = 0;
    if (tid < NSEG) s14[tid] = g_segmax[img * NSEG + tid];
    __syncthreads();

    float m = s14[0];
#pragma unroll
    for (int i = 1; i < NSEG; i++) m = fmaxf(m, s14[i]);
    const float thr = 0.7f * m;   // THRESH_FRAC * image max

    // local chunk ids within image: this thread's float4 covers chunks lc, lc+1
    const int lc = (((blockIdx.x & 7) << 8) + tid) << 1;
    if (fmaxf(v.x, v.y) >= thr) slist[atomicAdd(&scount, 1)] = lc;
    if (fmaxf(v.z, v.w) >= thr) slist[atomicAdd(&scount, 1)] = lc + 1;
    __syncthreads();
    const int n = scount;
    if (n == 0) return;

    const int wid  = tid >> 5;
    const int lane = tid & 31;
    const float SC = (1.0f / 12.0f);
    const float* __restrict__ xim = x + (size_t)img * HWSZ;

    const int b   = img >> 6;
    const int cch = img & 63;
    const float bi = bias[cch];
    const int half = lane >> 4;          // channel half (0: ci 0-31, 1: ci 32-63)
    const int px   = lane & 15;          // pixel index within chunk
    const float* __restrict__ wr = wt + (cch << 6) + half * 32;
    const float* __restrict__ xbase = x + ((size_t)(b << 6) + half * 32) * HWSZ;

    for (int li = wid; li < n; li += 8) {
        int rc  = slist[li];
        int q   = rc >> 4;
        int c0  = (rc & 15) << 4;

        int c  = c0 - 2 + lane;                 // field column
        int cc = (c < 0) ? -c : (c >= WW ? 2*WW - 2 - c : c);
        int cL = (cc == 0) ? 1 : cc - 1;        // reflect-101 col for x loads
        int cR = (cc == WW-1) ? WW-2 : cc + 1;

        int dlo = q - 2 < 0 ? 0 : q - 2;

        // Upfront parallel loads: 7 rows x 3 cols (independent -> MLP 21).
        float xr0[7], xr1[7], xr2[7];
#pragma unroll
        for (int j = 0; j < 7; ++j) {
            int rj = rrow(dlo - 1 + j) * WW;
            xr0[j] = xim[rj + cL];
            xr1[j] = xim[rj + cc];
            xr2[j] = xim[rj + cR];
        }
        float xq = xim[q * WW + cc];            // x at (q, cc) for the mask

        float ddx[5], ddxy[5], ddy2[5];
#pragma unroll
        for (int k = 0; k < 5; ++k) {           // d = dlo + k (k>span unused)
            float uL = fmaf(2.0f, xr0[k+1], xr0[k]) + xr0[k+2];
            float uR = fmaf(2.0f, xr2[k+1], xr2[k]) + xr2[k+2];
            float vL = xr0[k+2] - xr0[k];
            float vC = xr1[k+2] - xr1[k];
            float vR = xr2[k+2] - xr2[k];
            float dx = (uR - uL) * SC;
            float dy = (fmaf(2.0f, vC, vL) + vR) * SC;
            ddx[k]  = dx * dx;
            ddxy[k] = dx * dy;
            ddy2[k] = dy * dy;
        }

        float dstv = -CUDART_INF_F;
        for (int rr = q - 1; rr <= q + 1; ++rr) {
            if (rr < 0 || rr > HH - 1) continue;
            float sxx, sxy, syy;
            if (rr == 0) {
                sxx = fmaf(2.0f, ddx[CL(1 - dlo)],  ddx[CL(0 - dlo)]);
                sxy = fmaf(2.0f, ddxy[CL(1 - dlo)], ddxy[CL(0 - dlo)]);
                syy = fmaf(2.0f, ddy2[CL(1 - dlo)], ddy2[CL(0 - dlo)]);
            } else if (rr == HH - 1) {
                float p2a = ddx[CL(254 - dlo)]  + ddx[CL(255 - dlo)];
                float p2b = ddxy[CL(254 - dlo)] + ddxy[CL(255 - dlo)];
                float p2c = ddy2[CL(254 - dlo)] + ddy2[CL(255 - dlo)];
                sxx = fmaf(2.0f, p2a - ddx[CL(255 - dlo)],  ddx[CL(255 - dlo)]);
                sxy = fmaf(2.0f, p2b - ddxy[CL(255 - dlo)], ddxy[CL(255 - dlo)]);
                syy = fmaf(2.0f, p2c - ddy2[CL(255 - dlo)], ddy2[CL(255 - dlo)]);
            } else {
                sxx = (ddx[CL(rr - 1 - dlo)]  + ddx[CL(rr - dlo)])  + ddx[CL(rr + 1 - dlo)];
                sxy = (ddxy[CL(rr - 1 - dlo)] + ddxy[CL(rr - dlo)]) + ddxy[CL(rr + 1 - dlo)];
                syy = (ddy2[CL(rr - 1 - dlo)] + ddy2[CL(rr - dlo)]) + ddy2[CL(rr + 1 - dlo)];
            }
            float xxm = __shfl_up_sync(0xffffffffu, sxx, 1);
            float xxp = __shfl_down_sync(0xffffffffu, sxx, 1);
            float xym = __shfl_up_sync(0xffffffffu, sxy, 1);
            float xyp = __shfl_down_sync(0xffffffffu, sxy, 1);
            float yym = __shfl_up_sync(0xffffffffu, syy, 1);
            float yyp = __shfl_down_sync(0xffffffffu, syy, 1);
            float ixx = (xxm + sxx) + xxp;
            float ixy = (xym + sxy) + xyp;
            float iyy = (yym + syy) + yyp;
            float t1 = ixy * ixy;
            float det = fmaf(ixx, iyy, -t1);
            float tr  = ixx + iyy;
            float t2 = tr * tr;
            float Rv = fmaf(-0.04f, t2, det);
            if (c < 0 || c > WW - 1) Rv = -CUDART_INF_F;   // dilation clips
            float Rm = __shfl_up_sync(0xffffffffu, Rv, 1);
            float Rp = __shfl_down_sync(0xffffffffu, Rv, 1);
            float mm = fmaxf(fmaxf(Rm, Rv), Rp);
            dstv = fmaxf(dstv, mm);
        }

        bool flg = (lane >= 2) && (lane < 18) && (dstv >= thr);
        unsigned bal = __ballot_sync(0xffffffffu, flg);
        if (bal) {
            // pixel-per-lane conv for ALL 16 chunk pixels at once
            int pix = (q << 8) + c0 + px;
            const float* xp = xbase + pix;
            float acc = 0.0f;
#pragma unroll
            for (int j = 0; j < 32; ++j)
                acc = fmaf(wr[j], xp[(size_t)j * HWSZ], acc);
            acc += __shfl_down_sync(0xffffffffu, acc, 16);   // merge channel halves
            float dpix = __shfl_sync(0xffffffffu, dstv, px + 2);
            float xpix = __shfl_sync(0xffffffffu, xq,   px + 2);
            if (half == 0 && ((bal >> (px + 2)) & 1u)) {
                float y = fmaxf(acc + bi, 0.0f);
                float mask = (dpix > thr) ? 1.0f : xpix;     // tie keeps pixel
                out[(size_t)img * HWSZ + pix] = fmaf(mask, y, xpix);
            }
        }
    }
}

extern "C" void kernel_launch(void* const* d_in, const int* in_sizes, int n_in,
                              void* d_out, int out_size) {
    const float* x = (const float*)d_in[0];
    const float* w = (const float*)d_in[1];
    const float* b = (const float*)d_in[2];
    float* out = (float*)d_out;
    harris_kernel<<<NIMG * NSEG, 32>>>(x, out);
    detect_apply_kernel<<<NIMG * 8, 256>>>(x, w, b, out);
}

// round 12
// speedup vs baseline: 1.0595x; 1.0595x over previous
#include <cuda_runtime.h>
#include <math_constants.h>

#define HH 256
#define WW 256
#define NIMG 512          // B*C = 8*64
#define CCH 64
#define HWSZ 65536        // 256*256
#define NSEG 14           // segments per image (4x19 + 10x18 rows)
#define NCHUNK (NIMG * HH * 16)

// Scratch (static device globals — no runtime allocation)
__device__ float g_cmax32[NIMG * HH * 32];    // per-(row, lane=8col) max of dst
__device__ float g_segmax[NIMG * NSEG];       // per-segment max of dst
__device__ float g_tmax[NIMG];                // 0.7 * per-image max
__device__ int   g_list[NCHUNK];              // flagged chunk ids
__device__ int   g_count;

__device__ __forceinline__ int rrow(int r) {
    return r < 0 ? -r : (r >= HH ? 2*HH - 2 - r : r);
}

// clamp dynamic local-array index into [0,4] — prevents speculative
// out-of-frame LDL when ptxas flattens the border branches into selects
#define CL(i) (min(max((int)(i), 0), 4))

// ---------------------------------------------------------------------------
// Pass A: Harris response R -> per-lane chunk maxes of the 3x3-dilated field
// (dst itself never materialized), segment maxes, out=x copy fused into the
// stencil row loads. One warp per (image, segment); lane owns 8 cols.
// All FP contractions pinned with explicit fmaf so the apply path can
// recompute dst bit-identically.
// ---------------------------------------------------------------------------

// Load x row r (reflect-101). If the REQUESTED row lies in this segment,
// also store it to out (each segment row passes through here exactly once).
#define LOAD_XROW(r, dst_)  do {                                              \
    int rq__ = (r);                                                           \
    int rr__ = (rq__ < 0) ? -rq__ : ((rq__ >= HH) ? (2*HH - 2 - rq__) : rq__);\
    const float4* p__ = reinterpret_cast<const float4*>(xim + rr__ * WW + cb);\
    float4 q0__ = p__[0], q1__ = p__[1];                                      \
    dst_[0]=q0__.x; dst_[1]=q0__.y; dst_[2]=q0__.z; dst_[3]=q0__.w;           \
    dst_[4]=q1__.x; dst_[5]=q1__.y; dst_[6]=q1__.z; dst_[7]=q1__.w;           \
    if ((unsigned)(rq__ - r0) < (unsigned)seglen) {                           \
        float4* po__ = reinterpret_cast<float4*>(oim + rq__ * WW + cb);       \
        po__[0] = q0__; po__[1] = q1__;                                       \
    }                                                                         \
} while(0)

#define COMPUTE_DD(row, AX, AXY, AY) do {                                     \
    float xc__[8]; LOAD_XROW((row)+1, xc__);                                  \
    float u__[8], v__[8];                                                     \
    _Pragma("unroll")                                                         \
    for (int i=0;i<8;i++){ u__[i] = fmaf(2.0f, xb[i], xa[i]) + xc__[i];       \
                           v__[i] = xc__[i] - xa[i]; }                        \
    float uL__ = __shfl_up_sync(0xffffffffu, u__[7], 1);                      \
    float uR__ = __shfl_down_sync(0xffffffffu, u__[0], 1);                    \
    float vL__ = __shfl_up_sync(0xffffffffu, v__[7], 1);                      \
    float vR__ = __shfl_down_sync(0xffffffffu, v__[0], 1);                    \
    if (lane == 0)  { uL__ = u__[1]; vL__ = v__[1]; }                         \
    if (lane == 31) { uR__ = u__[6]; vR__ = v__[6]; }                         \
    _Pragma("unroll")                                                         \
    for (int i=0;i<8;i++){                                                    \
        float um1__ = (i==0)? uL__ : u__[i-1];                                \
        float up1__ = (i==7)? uR__ : u__[i+1];                                \
        float vm1__ = (i==0)? vL__ : v__[i-1];                                \
        float vp1__ = (i==7)? vR__ : v__[i+1];                                \
        float dx__ = (up1__ - um1__) * SC;                                    \
        float dy__ = (fmaf(2.0f, v__[i], vm1__) + vp1__) * SC;                \
        AX[i] = dx__*dx__; AXY[i] = dx__*dy__; AY[i] = dy__*dy__;             \
    }                                                                         \
    _Pragma("unroll")                                                         \
    for (int i=0;i<8;i++){ xa[i] = xb[i]; xb[i] = xc__[i]; }                  \
} while(0)

// Horizontal sums + R + per-lane row max h + emit chunkmax row q = PV-1.
#define EMIT_P(PV) do {                                                       \
    float xxL__ = __shfl_up_sync(0xffffffffu, sxx[7],1);                      \
    float xxR__ = __shfl_down_sync(0xffffffffu, sxx[0],1);                    \
    float xyL__ = __shfl_up_sync(0xffffffffu, sxy[7],1);                      \
    float xyR__ = __shfl_down_sync(0xffffffffu, sxy[0],1);                    \
    float yyL__ = __shfl_up_sync(0xffffffffu, syy[7],1);                      \
    float yyR__ = __shfl_down_sync(0xffffffffu, syy[0],1);                    \
    if (lane==0){  xxL__=sxx[1]; xyL__=sxy[1]; yyL__=syy[1]; }                \
    if (lane==31){ xxR__=sxx[6]; xyR__=sxy[6]; yyR__=syy[6]; }                \
    float Rv__[8];                                                            \
    _Pragma("unroll")                                                         \
    for (int i=0;i<8;i++){                                                    \
        float ixx = (((i==0)?xxL__:sxx[i-1]) + sxx[i]) + ((i==7)?xxR__:sxx[i+1]);\
        float ixy = (((i==0)?xyL__:sxy[i-1]) + sxy[i]) + ((i==7)?xyR__:sxy[i+1]);\
        float iyy = (((i==0)?yyL__:syy[i-1]) + syy[i]) + ((i==7)?yyR__:syy[i+1]);\
        float t1__ = ixy * ixy;                                               \
        float det__ = fmaf(ixx, iyy, -t1__);                                  \
        float tr__  = ixx + iyy;                                              \
        float t2__ = tr__ * tr__;                                             \
        Rv__[i] = fmaf(-0.04f, t2__, det__);                                  \
    }                                                                         \
    float RL__ = __shfl_up_sync(0xffffffffu, Rv__[7],1);                      \
    float RR__ = __shfl_down_sync(0xffffffffu, Rv__[0],1);                    \
    if (lane==0)  RL__ = -CUDART_INF_F;                                       \
    if (lane==31) RR__ = -CUDART_INF_F;                                       \
    float hc__ = fmaxf(RL__, RR__);                                           \
    _Pragma("unroll")                                                         \
    for (int i=0;i<8;i++) hc__ = fmaxf(hc__, Rv__[i]);                        \
    int q__ = (PV) - 1;                                                       \
    if (q__ >= r0) {                                                          \
        float cm__ = fmaxf(fmaxf(hb, ha), hc__);                              \
        lmax = fmaxf(lmax, cm__);                                             \
        g_cmax32[((img<<8)+q__)*32 + lane] = cm__;                            \
    }                                                                         \
    hb = ha; ha = hc__;                                                       \
} while(0)

__global__ void __launch_bounds__(32, 16) harris_kernel(const float* __restrict__ x,
                                                        float* __restrict__ out) {
    if (blockIdx.x == 0 && threadIdx.x == 0) g_count = 0;   // reset list
    const int img  = blockIdx.x / NSEG;
    const int seg  = blockIdx.x - img * NSEG;
    const int lane = threadIdx.x;
    const int cb   = lane * 8;
    const float* __restrict__ xim = x + (size_t)img * HWSZ;
    float* __restrict__ oim = out + (size_t)img * HWSZ;

    // 4 segments of 19 rows then 10 of 18 rows (total 256); grid 7168 warps
    // = 3.03 waves at 16 resident blocks/SM (kills wave quantization).
    const int r0     = seg * 18 + min(seg, 4);
    const int seglen = 18 + (seg < 4 ? 1 : 0);
    const int r1     = r0 + seglen;

    const float SC = (1.0f / 12.0f);   // SOBEL_SCALE
    float xa[8], xb[8];
    float p2x[8], p2y[8], p2z[8];      // P2 = dd(p-1)+dd(p)   (xx,xy,yy)
    float cx[8],  cy[8],  cz[8];       // C  = dd(p)
    float ha = -CUDART_INF_F, hb = -CUDART_INF_F;  // h(p-1), h(p-2)
    float lmax = -CUDART_INF_F;

    int pstart;
    if (r0 == 0) {
        LOAD_XROW(-1, xa);
        LOAD_XROW(0,  xb);
        COMPUTE_DD(0, cx, cy, cz);
#pragma unroll
        for (int i=0;i<8;i++){ p2x[i]=cx[i]+cx[i]; p2y[i]=cy[i]+cy[i]; p2z[i]=cz[i]+cz[i]; }
        // peeled p == 0 iteration (emits q=-1: nothing; shifts ha/hb)
        {
            float nx[8], ny[8], nz[8];
            COMPUTE_DD(1, nx, ny, nz);
            float sxx[8], sxy[8], syy[8];
#pragma unroll
            for (int i=0;i<8;i++){ sxx[i]=fmaf(2.0f, nx[i], cx[i]);
                                   sxy[i]=fmaf(2.0f, ny[i], cy[i]);
                                   syy[i]=fmaf(2.0f, nz[i], cz[i]); }
#pragma unroll
            for (int i=0;i<8;i++){ p2x[i]=cx[i]+nx[i]; cx[i]=nx[i];
                                   p2y[i]=cy[i]+ny[i]; cy[i]=ny[i];
                                   p2z[i]=cz[i]+nz[i]; cz[i]=nz[i]; }
            EMIT_P(0);
        }
        pstart = 1;
    } else {
        float d1x[8], d1y[8], d1z[8];
        LOAD_XROW(r0 - 3, xa);
        LOAD_XROW(r0 - 2, xb);
        COMPUTE_DD(r0 - 2, d1x, d1y, d1z);
        COMPUTE_DD(r0 - 1, cx, cy, cz);
#pragma unroll
        for (int i=0;i<8;i++){ p2x[i]=d1x[i]+cx[i]; p2y[i]=d1y[i]+cy[i]; p2z[i]=d1z[i]+cz[i]; }
        pstart = r0 - 1;
    }

    const int pend = (r1 == HH) ? (HH - 1) : (r1 + 1);
#pragma unroll 2
    for (int p = pstart; p < pend; ++p) {
        float nx[8], ny[8], nz[8];
        COMPUTE_DD(p+1, nx, ny, nz);
        float sxx[8], sxy[8], syy[8];
#pragma unroll
        for (int i=0;i<8;i++){ sxx[i]=p2x[i]+nx[i];
                               sxy[i]=p2y[i]+ny[i];
                               syy[i]=p2z[i]+nz[i]; }
#pragma unroll
        for (int i=0;i<8;i++){ p2x[i]=cx[i]+nx[i]; cx[i]=nx[i];
                               p2y[i]=cy[i]+ny[i]; cy[i]=ny[i];
                               p2z[i]=cz[i]+nz[i]; cz[i]=nz[i]; }
        EMIT_P(p);
    }

    if (r1 == HH) {
        // peel p = 255: vertical sum = dd(255) + 2*(p2-dd(255)) (= +2*dd(254))
        float sxx[8], sxy[8], syy[8];
#pragma unroll
        for (int i=0;i<8;i++){
            sxx[i] = fmaf(2.0f, p2x[i] - cx[i], cx[i]);
            sxy[i] = fmaf(2.0f, p2y[i] - cy[i], cy[i]);
            syy[i] = fmaf(2.0f, p2z[i] - cz[i], cz[i]);
        }
        EMIT_P(255);
        // bottom image row: chunkmax(255) = max(h(254), h(255))
        float cm = fmaxf(hb, ha);
        lmax = fmaxf(lmax, cm);
        g_cmax32[((img<<8)+(HH-1))*32 + lane] = cm;
    }

#pragma unroll
    for (int o=16;o;o>>=1) lmax = fmaxf(lmax, __shfl_xor_sync(0xffffffffu, lmax, o));
    if (lane == 0) g_segmax[img * NSEG + seg] = lmax;
}

// ---------------------------------------------------------------------------
// Scan: compute t per image, compact flagged chunks (cmax >= t) into g_list
// with warp-aggregated atomics. Each thread covers 2 chunks via one float4.
// Grid: 4096 blocks x 256 (8 blocks per image).
// ---------------------------------------------------------------------------
__global__ void scan_kernel() {
    __shared__ float s14[NSEG];
    const int img = blockIdx.x >> 3;
    if (threadIdx.x < NSEG) s14[threadIdx.x] = g_segmax[img * NSEG + threadIdx.x];
    // cmax load in flight before the sync
    const int pair = blockIdx.x * 256 + threadIdx.x;      // 2 chunks per thread
    const float4 v = *reinterpret_cast<const float4*>(g_cmax32 + (size_t)pair * 4);
    __syncthreads();
    float m = s14[0];
#pragma unroll
    for (int i = 1; i < NSEG; i++) m = fmaxf(m, s14[i]);
    const float t = 0.7f * m;   // THRESH_FRAC
    if ((blockIdx.x & 7) == 0 && threadIdx.x == 0) g_tmax[img] = t;

    int cid0 = pair * 2;
    bool f0 = fmaxf(v.x, v.y) >= t;
    bool f1 = fmaxf(v.z, v.w) >= t;

    unsigned b0 = __ballot_sync(0xffffffffu, f0);
    unsigned b1 = __ballot_sync(0xffffffffu, f1);
    int n0 = __popc(b0);
    int tot = n0 + __popc(b1);
    if (tot) {
        int lane = threadIdx.x & 31;
        unsigned lt = (1u << lane) - 1u;
        int basep = 0;
        if (lane == 0) basep = atomicAdd(&g_count, tot);
        basep = __shfl_sync(0xffffffffu, basep, 0);
        if (f0) g_list[basep + __popc(b0 & lt)] = cid0;
        if (f1) g_list[basep + n0 + __popc(b1 & lt)] = cid0 + 1;
    }
}

// ---------------------------------------------------------------------------
// Apply: 16K warps grid-stride the compacted list — one chunk per warp,
// declustered across the whole chip. Per chunk: 21 upfront parallel x loads,
// recompute dst bit-identical to pass A, then PIXEL-PER-LANE conv: lanes
// 0-15 own the chunk's 16 pixels (channels 0-31), lanes 16-31 same pixels
// (channels 32-63); 32 independent strided loads (one latency window), one
// shfl merge, predicated store.
// ---------------------------------------------------------------------------
__global__ void apply_kernel(const float* __restrict__ x, const float* __restrict__ wt,
                             const float* __restrict__ bias, float* __restrict__ out) {
    const int gwarp  = (blockIdx.x * blockDim.x + threadIdx.x) >> 5;
    const int nwarps = (gridDim.x * blockDim.x) >> 5;
    const int lane = threadIdx.x & 31;
    const float SC = (1.0f / 12.0f);
    const int total = g_count;
    const int half = lane >> 4;          // channel half (0: ci 0-31, 1: ci 32-63)
    const int px   = lane & 15;          // pixel index within chunk

    for (int li = gwarp; li < total; li += nwarps) {
        int cid = g_list[li];
        int img = cid >> 12;
        int rc  = cid & 4095;
        int q   = rc >> 4;
        int c0  = (rc & 15) << 4;
        float t = g_tmax[img];
        const float* __restrict__ xim = x + (size_t)img * HWSZ;

        int c  = c0 - 2 + lane;                 // field column
        int cc = (c < 0) ? -c : (c >= WW ? 2*WW - 2 - c : c);
        int cL = (cc == 0) ? 1 : cc - 1;        // reflect-101 col for x loads
        int cR = (cc == WW-1) ? WW-2 : cc + 1;

        int dlo = q - 2 < 0 ? 0 : q - 2;

        // Upfront parallel loads: 7 rows x 3 cols (independent -> MLP 21).
        float xr0[7], xr1[7], xr2[7];
#pragma unroll
        for (int j = 0; j < 7; ++j) {
            int rj = rrow(dlo - 1 + j) * WW;
            xr0[j] = xim[rj + cL];
            xr1[j] = xim[rj + cc];
            xr2[j] = xim[rj + cR];
        }
        float xq = xim[q * WW + cc];            // x at (q, cc) for the mask

        float ddx[5], ddxy[5], ddy2[5];
#pragma unroll
        for (int k = 0; k < 5; ++k) {           // d = dlo + k (k>span unused)
            float uL = fmaf(2.0f, xr0[k+1], xr0[k]) + xr0[k+2];
            float uR = fmaf(2.0f, xr2[k+1], xr2[k]) + xr2[k+2];
            float vL = xr0[k+2] - xr0[k];
            float vC = xr1[k+2] - xr1[k];
            float vR = xr2[k+2] - xr2[k];
            float dx = (uR - uL) * SC;
            float dy = (fmaf(2.0f, vC, vL) + vR) * SC;
            ddx[k]  = dx * dx;
            ddxy[k] = dx * dy;
            ddy2[k] = dy * dy;
        }

        float dstv = -CUDART_INF_F;
        for (int rr = q - 1; rr <= q + 1; ++rr) {
            if (rr < 0 || rr > HH - 1) continue;
            float sxx, sxy, syy;
            if (rr == 0) {
                sxx = fmaf(2.0f, ddx[CL(1 - dlo)],  ddx[CL(0 - dlo)]);
                sxy = fmaf(2.0f, ddxy[CL(1 - dlo)], ddxy[CL(0 - dlo)]);
                syy = fmaf(2.0f, ddy2[CL(1 - dlo)], ddy2[CL(0 - dlo)]);
            } else if (rr == HH - 1) {
                float p2a = ddx[CL(254 - dlo)]  + ddx[CL(255 - dlo)];
                float p2b = ddxy[CL(254 - dlo)] + ddxy[CL(255 - dlo)];
                float p2c = ddy2[CL(254 - dlo)] + ddy2[CL(255 - dlo)];
                sxx = fmaf(2.0f, p2a - ddx[CL(255 - dlo)],  ddx[CL(255 - dlo)]);
                sxy = fmaf(2.0f, p2b - ddxy[CL(255 - dlo)], ddxy[CL(255 - dlo)]);
                syy = fmaf(2.0f, p2c - ddy2[CL(255 - dlo)], ddy2[CL(255 - dlo)]);
            } else {
                sxx = (ddx[CL(rr - 1 - dlo)]  + ddx[CL(rr - dlo)])  + ddx[CL(rr + 1 - dlo)];
                sxy = (ddxy[CL(rr - 1 - dlo)] + ddxy[CL(rr - dlo)]) + ddxy[CL(rr + 1 - dlo)];
                syy = (ddy2[CL(rr - 1 - dlo)] + ddy2[CL(rr - dlo)]) + ddy2[CL(rr + 1 - dlo)];
            }
            float xxm = __shfl_up_sync(0xffffffffu, sxx, 1);
            float xxp = __shfl_down_sync(0xffffffffu, sxx, 1);
            float xym = __shfl_up_sync(0xffffffffu, sxy, 1);
            float xyp = __shfl_down_sync(0xffffffffu, sxy, 1);
            float yym = __shfl_up_sync(0xffffffffu, syy, 1);
            float yyp = __shfl_down_sync(0xffffffffu, syy, 1);
            float ixx = (xxm + sxx) + xxp;
            float ixy = (xym + sxy) + xyp;
            float iyy = (yym + syy) + yyp;
            float t1 = ixy * ixy;
            float det = fmaf(ixx, iyy, -t1);
            float tr  = ixx + iyy;
            float t2 = tr * tr;
            float Rv = fmaf(-0.04f, t2, det);
            if (c < 0 || c > WW - 1) Rv = -CUDART_INF_F;   // dilation clips
            float Rm = __shfl_up_sync(0xffffffffu, Rv, 1);
            float Rp = __shfl_down_sync(0xffffffffu, Rv, 1);
            float mm = fmaxf(fmaxf(Rm, Rv), Rp);
            dstv = fmaxf(dstv, mm);
        }

        bool flg = (lane >= 2) && (lane < 18) && (dstv >= t);
        unsigned bal = __ballot_sync(0xffffffffu, flg);
        if (bal) {
            int b   = img >> 6;
            int cch = img & 63;
            float bi = bias[cch];
            const float* wr = wt + (cch << 6) + half * 32;
            const float* xp = x + ((size_t)(b << 6) + half * 32) * HWSZ
                                + ((q << 8) + c0 + px);
            float acc = 0.0f;
#pragma unroll
            for (int j = 0; j < 32; ++j)
                acc = fmaf(wr[j], xp[(size_t)j * HWSZ], acc);
            acc += __shfl_down_sync(0xffffffffu, acc, 16);   // merge channel halves
            float dpix = __shfl_sync(0xffffffffu, dstv, px + 2);
            float xpix = __shfl_sync(0xffffffffu, xq,   px + 2);
            if (half == 0 && ((bal >> (px + 2)) & 1u)) {
                float y = fmaxf(acc + bi, 0.0f);
                float mask = (dpix > t) ? 1.0f : xpix;       // tie keeps pixel
                out[(size_t)img * HWSZ + ((q << 8) + c0 + px)] = fmaf(mask, y, xpix);
            }
        }
    }
}

extern "C" void kernel_launch(void* const* d_in, const int* in_sizes, int n_in,
                              void* d_out, int out_size) {
    const float* x = (const float*)d_in[0];
    const float* w = (const float*)d_in[1];
    const float* b = (const float*)d_in[2];
    float* out = (float*)d_out;
    harris_kernel<<<NIMG * NSEG, 32>>>(x, out);
    scan_kernel<<<4096, 256>>>();
    apply_kernel<<<2048, 256>>>(x, w, b, out);
}